// round 1
// baseline (speedup 1.0000x reference)
#include <cuda_runtime.h>

// DiscriminatorLoss: out = mean( (s==other_s ? +1 : -1) * x ), N = 33554432.
// Pure HBM-bound streaming reduction: 12 B/elem read -> ~402 MB total.
//
// Two-kernel deterministic reduction (no float atomics):
//   k1: 1024 blocks x 256 threads, vec4 grid-stride, block-reduce -> g_partials
//   k2: 1 block x 1024 threads folds partials, scales by 1/N.

#define RBLOCKS 1024
#define RTHREADS 256

__device__ float g_partials[RBLOCKS];

__global__ __launch_bounds__(RTHREADS)
void disc_loss_reduce(const int* __restrict__ s,
                      const int* __restrict__ o,
                      const float* __restrict__ x,
                      int n4)
{
    const int4*   s4 = reinterpret_cast<const int4*>(s);
    const int4*   o4 = reinterpret_cast<const int4*>(o);
    const float4* x4 = reinterpret_cast<const float4*>(x);

    float acc = 0.0f;
    const int stride = gridDim.x * blockDim.x;
    int i = blockIdx.x * blockDim.x + threadIdx.x;

    // 2-way manual unroll of the grid-stride loop for extra MLP.
    for (; i + stride < n4; i += 2 * stride) {
        int4   sa = s4[i],          oa = o4[i];
        int4   sb = s4[i + stride], ob = o4[i + stride];
        float4 xa = x4[i];
        float4 xb = x4[i + stride];

        acc += (sa.x == oa.x) ? xa.x : -xa.x;
        acc += (sa.y == oa.y) ? xa.y : -xa.y;
        acc += (sa.z == oa.z) ? xa.z : -xa.z;
        acc += (sa.w == oa.w) ? xa.w : -xa.w;
        acc += (sb.x == ob.x) ? xb.x : -xb.x;
        acc += (sb.y == ob.y) ? xb.y : -xb.y;
        acc += (sb.z == ob.z) ? xb.z : -xb.z;
        acc += (sb.w == ob.w) ? xb.w : -xb.w;
    }
    for (; i < n4; i += stride) {
        int4   sv = s4[i], ov = o4[i];
        float4 xv = x4[i];
        acc += (sv.x == ov.x) ? xv.x : -xv.x;
        acc += (sv.y == ov.y) ? xv.y : -xv.y;
        acc += (sv.z == ov.z) ? xv.z : -xv.z;
        acc += (sv.w == ov.w) ? xv.w : -xv.w;
    }

    // Warp reduce
    #pragma unroll
    for (int off = 16; off > 0; off >>= 1)
        acc += __shfl_xor_sync(0xffffffffu, acc, off);

    __shared__ float warp_sums[RTHREADS / 32];
    if ((threadIdx.x & 31) == 0)
        warp_sums[threadIdx.x >> 5] = acc;
    __syncthreads();

    if (threadIdx.x < 32) {
        float v = (threadIdx.x < (RTHREADS / 32)) ? warp_sums[threadIdx.x] : 0.0f;
        #pragma unroll
        for (int off = (RTHREADS / 64); off > 0; off >>= 1)
            v += __shfl_xor_sync(0xffffffffu, v, off);
        if (threadIdx.x == 0)
            g_partials[blockIdx.x] = v;
    }
}

__global__ __launch_bounds__(1024)
void disc_loss_finalize(float* __restrict__ out, float inv_n)
{
    float v = g_partials[threadIdx.x];  // blockDim.x == RBLOCKS == 1024

    #pragma unroll
    for (int off = 16; off > 0; off >>= 1)
        v += __shfl_xor_sync(0xffffffffu, v, off);

    __shared__ float warp_sums[32];
    if ((threadIdx.x & 31) == 0)
        warp_sums[threadIdx.x >> 5] = v;
    __syncthreads();

    if (threadIdx.x < 32) {
        float t = warp_sums[threadIdx.x];
        #pragma unroll
        for (int off = 16; off > 0; off >>= 1)
            t += __shfl_xor_sync(0xffffffffu, t, off);
        if (threadIdx.x == 0)
            out[0] = t * inv_n;
    }
}

extern "C" void kernel_launch(void* const* d_in, const int* in_sizes, int n_in,
                              void* d_out, int out_size)
{
    const int*   s = (const int*)d_in[0];
    const int*   o = (const int*)d_in[1];
    const float* x = (const float*)d_in[2];
    float* out = (float*)d_out;

    const int n  = in_sizes[0];
    const int n4 = n >> 2;  // N divisible by 4

    disc_loss_reduce<<<RBLOCKS, RTHREADS>>>(s, o, x, n4);
    disc_loss_finalize<<<1, 1024>>>(out, 1.0f / (float)n);
}

// round 2
// speedup vs baseline: 1.0005x; 1.0005x over previous
#include <cuda_runtime.h>

// DiscriminatorLoss: out = mean( (s==other_s ? +1 : -1) * x ), N = 33554432.
// HBM-bound streaming reduction (~402 MB read). Single fused kernel:
// grid-stride vec4 loop -> block reduce -> g_partials; last-arriving block
// (ticket via atomicInc with wrap, self-resetting for graph replay) folds the
// 1024 partials in a fixed order and writes mean. Deterministic.

#define RBLOCKS 1024
#define RTHREADS 256

__device__ float g_partials[RBLOCKS];
__device__ unsigned int g_ticket;   // zero-initialized; wraps back to 0

__global__ __launch_bounds__(RTHREADS)
void disc_loss_fused(const int* __restrict__ s,
                     const int* __restrict__ o,
                     const float* __restrict__ x,
                     int n4, float inv_n,
                     float* __restrict__ out)
{
    const int4*   s4 = reinterpret_cast<const int4*>(s);
    const int4*   o4 = reinterpret_cast<const int4*>(o);
    const float4* x4 = reinterpret_cast<const float4*>(x);

    float acc = 0.0f;
    const int stride = gridDim.x * blockDim.x;
    int i = blockIdx.x * blockDim.x + threadIdx.x;

    // 2-way unrolled grid-stride loop: 6 independent 128-bit loads in flight
    // per iteration for MLP.
    for (; i + stride < n4; i += 2 * stride) {
        int4   sa = s4[i],          oa = o4[i];
        int4   sb = s4[i + stride], ob = o4[i + stride];
        float4 xa = x4[i];
        float4 xb = x4[i + stride];

        acc += (sa.x == oa.x) ? xa.x : -xa.x;
        acc += (sa.y == oa.y) ? xa.y : -xa.y;
        acc += (sa.z == oa.z) ? xa.z : -xa.z;
        acc += (sa.w == oa.w) ? xa.w : -xa.w;
        acc += (sb.x == ob.x) ? xb.x : -xb.x;
        acc += (sb.y == ob.y) ? xb.y : -xb.y;
        acc += (sb.z == ob.z) ? xb.z : -xb.z;
        acc += (sb.w == ob.w) ? xb.w : -xb.w;
    }
    for (; i < n4; i += stride) {
        int4   sv = s4[i], ov = o4[i];
        float4 xv = x4[i];
        acc += (sv.x == ov.x) ? xv.x : -xv.x;
        acc += (sv.y == ov.y) ? xv.y : -xv.y;
        acc += (sv.z == ov.z) ? xv.z : -xv.z;
        acc += (sv.w == ov.w) ? xv.w : -xv.w;
    }

    // Block reduce
    #pragma unroll
    for (int off = 16; off > 0; off >>= 1)
        acc += __shfl_xor_sync(0xffffffffu, acc, off);

    __shared__ float warp_sums[RTHREADS / 32];
    __shared__ bool  s_last;
    if ((threadIdx.x & 31) == 0)
        warp_sums[threadIdx.x >> 5] = acc;
    __syncthreads();

    if (threadIdx.x < 32) {
        float v = (threadIdx.x < (RTHREADS / 32)) ? warp_sums[threadIdx.x] : 0.0f;
        #pragma unroll
        for (int off = (RTHREADS / 64); off > 0; off >>= 1)
            v += __shfl_xor_sync(0xffffffffu, v, off);
        if (threadIdx.x == 0) {
            g_partials[blockIdx.x] = v;
            __threadfence();
            // atomicInc wraps: old==RBLOCKS-1 -> 0, so it self-resets for the
            // next graph replay. The block drawing the last ticket finalizes.
            unsigned int t = atomicInc(&g_ticket, RBLOCKS - 1u);
            s_last = (t == RBLOCKS - 1u);
        }
    }
    __syncthreads();

    if (s_last) {
        // Fixed-order fold of all partials -> deterministic output.
        const volatile float* p = g_partials;
        float v = p[threadIdx.x]
                + p[threadIdx.x + 256]
                + p[threadIdx.x + 512]
                + p[threadIdx.x + 768];

        #pragma unroll
        for (int off = 16; off > 0; off >>= 1)
            v += __shfl_xor_sync(0xffffffffu, v, off);

        if ((threadIdx.x & 31) == 0)
            warp_sums[threadIdx.x >> 5] = v;
        __syncthreads();

        if (threadIdx.x < 32) {
            float t = (threadIdx.x < (RTHREADS / 32)) ? warp_sums[threadIdx.x] : 0.0f;
            #pragma unroll
            for (int off = (RTHREADS / 64); off > 0; off >>= 1)
                t += __shfl_xor_sync(0xffffffffu, t, off);
            if (threadIdx.x == 0)
                out[0] = t * inv_n;
        }
    }
}

extern "C" void kernel_launch(void* const* d_in, const int* in_sizes, int n_in,
                              void* d_out, int out_size)
{
    const int*   s = (const int*)d_in[0];
    const int*   o = (const int*)d_in[1];
    const float* x = (const float*)d_in[2];
    float* out = (float*)d_out;

    const int n  = in_sizes[0];
    const int n4 = n >> 2;

    disc_loss_fused<<<RBLOCKS, RTHREADS>>>(s, o, x, n4, 1.0f / (float)n, out);
}